// round 1
// baseline (speedup 1.0000x reference)
#include <cuda_runtime.h>
#include <math.h>

// Problem constants
#define BB   128
#define NN   196
#define CC   768
#define HH   8
#define HD   96
#define MROWS (BB*NN)   // 25088
#define BHD   (BB*HH)   // 1024

// -------- device scratch (no runtime allocation allowed) --------
__device__ float g_Q[(size_t)MROWS*CC];
__device__ float g_K[(size_t)MROWS*CC];
__device__ float g_V[(size_t)MROWS*CC];
__device__ float g_A[(size_t)MROWS*CC];
__device__ float g_KV[(size_t)BHD*HD*HD];
__device__ float g_KS[(size_t)BHD*HD];

// ======================= tiled SGEMM =======================
// C[M,N] = A[M,K] @ B[K,N] + bias[N]  (+ pos_enc broadcast over batch if addPos)
#define BM 128
#define BN 128
#define BK 32

__global__ __launch_bounds__(256) void sgemm_kernel(
    const float* __restrict__ A, const float* __restrict__ B,
    const float* __restrict__ bias, const float* __restrict__ pos,
    float* __restrict__ C, int M, int N, int K, int addPos)
{
    __shared__ __align__(16) float As[BK][BM + 4];
    __shared__ __align__(16) float Bs[BK][BN];

    const int tid = threadIdx.x;
    const int bm = blockIdx.y * BM;
    const int bn = blockIdx.x * BN;
    const int tx = tid & 15;
    const int ty = tid >> 4;

    const int aRow = tid >> 3;         // 0..31
    const int aCol = (tid & 7) << 2;   // 0,4,...,28
    const int bRow = tid >> 5;         // 0..7
    const int bCol = (tid & 31) << 2;  // 0,4,...,124

    float acc[8][8];
#pragma unroll
    for (int i = 0; i < 8; i++)
#pragma unroll
        for (int j = 0; j < 8; j++) acc[i][j] = 0.f;

    for (int k0 = 0; k0 < K; k0 += BK) {
#pragma unroll
        for (int it = 0; it < 4; it++) {
            float4 a4 = *(const float4*)(A + (size_t)(bm + aRow + it * 32) * K + k0 + aCol);
            As[aCol + 0][aRow + it * 32] = a4.x;
            As[aCol + 1][aRow + it * 32] = a4.y;
            As[aCol + 2][aRow + it * 32] = a4.z;
            As[aCol + 3][aRow + it * 32] = a4.w;
            *(float4*)(&Bs[bRow + it * 8][bCol]) =
                *(const float4*)(B + (size_t)(k0 + bRow + it * 8) * N + bn + bCol);
        }
        __syncthreads();

#pragma unroll 8
        for (int kk = 0; kk < BK; kk++) {
            float af[8], bf[8];
            *(float4*)(af)     = *(const float4*)&As[kk][ty * 8];
            *(float4*)(af + 4) = *(const float4*)&As[kk][ty * 8 + 4];
            *(float4*)(bf)     = *(const float4*)&Bs[kk][tx * 8];
            *(float4*)(bf + 4) = *(const float4*)&Bs[kk][tx * 8 + 4];
#pragma unroll
            for (int i = 0; i < 8; i++)
#pragma unroll
                for (int j = 0; j < 8; j++)
                    acc[i][j] = fmaf(af[i], bf[j], acc[i][j]);
        }
        __syncthreads();
    }

#pragma unroll
    for (int i = 0; i < 8; i++) {
        int row = bm + ty * 8 + i;
        int prow = row % NN;
#pragma unroll
        for (int j = 0; j < 8; j += 4) {
            int col = bn + tx * 8 + j;
            float4 r = make_float4(acc[i][j], acc[i][j + 1], acc[i][j + 2], acc[i][j + 3]);
            r.x += bias[col];     r.y += bias[col + 1];
            r.z += bias[col + 2]; r.w += bias[col + 3];
            if (addPos) {
                float4 p = *(const float4*)(pos + (size_t)prow * N + col);
                r.x += p.x; r.y += p.y; r.z += p.z; r.w += p.w;
            }
            *(float4*)(C + (size_t)row * N + col) = r;
        }
    }
}

// ======================= focusing kernel =======================
// t = (relu(t)+1e-6)/softplus(sp); then t = t^3 * sqrt(sum t^2 / sum t^6)
// one block per row; grid.y: 0 -> Q, 1 -> K
__global__ __launch_bounds__(256) void focus_kernel(
    float* __restrict__ q, float* __restrict__ k, const float* __restrict__ sp)
{
    float* t = blockIdx.y ? k : q;
    float* p = t + (size_t)blockIdx.x * CC;
    const int tid = threadIdx.x;

    float r[3];
    float s2 = 0.f, s6 = 0.f;
#pragma unroll
    for (int i = 0; i < 3; i++) {
        int c = tid + i * 256;
        float s = sp[c];
        float sc = (s > 20.f) ? s : log1pf(expf(s));
        float v = fmaxf(p[c], 0.f) + 1e-6f;
        v = v / sc;
        r[i] = v;
        float v2 = v * v;
        s2 += v2;
        float v3 = v2 * v;
        s6 += v3 * v3;
    }

    __shared__ float red2[8], red6[8];
    unsigned lane = tid & 31, wid = tid >> 5;
#pragma unroll
    for (int o = 16; o > 0; o >>= 1) {
        s2 += __shfl_down_sync(0xffffffffu, s2, o);
        s6 += __shfl_down_sync(0xffffffffu, s6, o);
    }
    if (lane == 0) { red2[wid] = s2; red6[wid] = s6; }
    __syncthreads();
    float t2 = 0.f, t6 = 0.f;
#pragma unroll
    for (int w = 0; w < 8; w++) { t2 += red2[w]; t6 += red6[w]; }
    float f = sqrtf(t2 / t6);

#pragma unroll
    for (int i = 0; i < 3; i++) {
        int c = tid + i * 256;
        float v = r[i];
        p[c] = v * v * v * f;
    }
}

// ======================= ksum =======================
// ksum[bh][c] = sum_j k[b, j, h*HD+c]
__global__ void ksum_kernel(const float* __restrict__ k, float* __restrict__ ksum)
{
    int bh = blockIdx.x;
    int b = bh >> 3, h = bh & 7;
    int c = threadIdx.x;
    const float* base = k + (size_t)b * NN * CC + h * HD + c;
    float s = 0.f;
#pragma unroll 4
    for (int j = 0; j < NN; j++) s += base[(size_t)j * CC];
    ksum[bh * HD + c] = s;
}

// ======================= kv = k^T v per (b,h) =======================
__global__ __launch_bounds__(256) void kv_kernel(
    const float* __restrict__ k, const float* __restrict__ v, float* __restrict__ kv)
{
    int bh = blockIdx.x;
    int b = bh >> 3, h = bh & 7;
    __shared__ float ks[28][HD];
    __shared__ float vs[28][HD];
    const int tid = threadIdx.x;
    const int ty = tid >> 4;   // 0..15 -> rows c
    const int tx = tid & 15;   // 0..15 -> cols d

    float acc[6][6];
#pragma unroll
    for (int i = 0; i < 6; i++)
#pragma unroll
        for (int j = 0; j < 6; j++) acc[i][j] = 0.f;

    const float* kb = k + (size_t)b * NN * CC + h * HD;
    const float* vb = v + (size_t)b * NN * CC + h * HD;

    for (int j0 = 0; j0 < NN; j0 += 28) {
        for (int idx = tid; idx < 28 * HD; idx += 256) {
            int j = idx / HD, c = idx % HD;
            ks[j][c] = kb[(size_t)(j0 + j) * CC + c];
            vs[j][c] = vb[(size_t)(j0 + j) * CC + c];
        }
        __syncthreads();
#pragma unroll 7
        for (int j = 0; j < 28; j++) {
            float kf[6], vf[6];
#pragma unroll
            for (int i = 0; i < 6; i++) kf[i] = ks[j][ty * 6 + i];
#pragma unroll
            for (int i = 0; i < 6; i++) vf[i] = vs[j][tx * 6 + i];
#pragma unroll
            for (int i = 0; i < 6; i++)
#pragma unroll
                for (int l = 0; l < 6; l++)
                    acc[i][l] = fmaf(kf[i], vf[l], acc[i][l]);
        }
        __syncthreads();
    }

#pragma unroll
    for (int i = 0; i < 6; i++)
#pragma unroll
        for (int l = 0; l < 6; l++)
            kv[(size_t)bh * HD * HD + (ty * 6 + i) * HD + tx * 6 + l] = acc[i][l];
}

// ======================= attention output (z fused) =======================
// out[i][d] = (1/(q_i . ksum + 1e-6)) * sum_c q[i][c] * kv[c][d]
__global__ __launch_bounds__(224) void attnout_kernel(
    const float* __restrict__ q, const float* __restrict__ kv,
    const float* __restrict__ ksum, float* __restrict__ outb)
{
    int bh = blockIdx.x;
    int b = bh >> 3, h = bh & 7;
    __shared__ __align__(16) float kvs[HD * HD];
    __shared__ float ksm[HD];
    const int tid = threadIdx.x;

    for (int idx = tid; idx < HD * HD; idx += 224)
        kvs[idx] = kv[(size_t)bh * HD * HD + idx];
    if (tid < HD) ksm[tid] = ksum[bh * HD + tid];
    __syncthreads();

    if (tid < NN) {
        const float* qr = q + ((size_t)b * NN + tid) * CC + h * HD;
        float zi = 0.f;
#pragma unroll 8
        for (int c = 0; c < HD; c++) zi += qr[c] * ksm[c];
        zi = 1.f / (zi + 1e-6f);

        float4 acc[24];
#pragma unroll
        for (int d = 0; d < 24; d++) acc[d] = make_float4(0.f, 0.f, 0.f, 0.f);

        for (int c = 0; c < HD; c++) {
            float qv = qr[c];
            const float4* kr = (const float4*)(kvs + c * HD);
#pragma unroll
            for (int d = 0; d < 24; d++) {
                float4 k4 = kr[d];
                acc[d].x = fmaf(qv, k4.x, acc[d].x);
                acc[d].y = fmaf(qv, k4.y, acc[d].y);
                acc[d].z = fmaf(qv, k4.z, acc[d].z);
                acc[d].w = fmaf(qv, k4.w, acc[d].w);
            }
        }

        float* orow = outb + ((size_t)b * NN + tid) * CC + h * HD;
#pragma unroll
        for (int d = 0; d < 24; d++) {
            float4 r = acc[d];
            r.x *= zi; r.y *= zi; r.z *= zi; r.w *= zi;
            *(float4*)(orow + d * 4) = r;
        }
    }
}

// ======================= depthwise 5x5 conv on v (14x14) =======================
// outb += dwc(v) ; grid: (BHD, 2 channel halves), 48 channels per block
__global__ __launch_bounds__(224) void dwc_kernel(
    const float* __restrict__ v, const float* __restrict__ w,
    const float* __restrict__ bias, float* __restrict__ outb)
{
    int bh = blockIdx.x;
    int b = bh >> 3, h = bh & 7;
    int c0 = blockIdx.y * 48;

    __shared__ float vs[NN * 49];   // padded stride 49 -> conflict-free
    __shared__ float ws[48 * 25];
    __shared__ float bs[48];
    const int tid = threadIdx.x;

    for (int idx = tid; idx < NN * 48; idx += 224) {
        int p = idx / 48, c = idx % 48;
        vs[p * 49 + c] = v[((size_t)b * NN + p) * CC + h * HD + c0 + c];
    }
    for (int idx = tid; idx < 48 * 25; idx += 224) ws[idx] = w[c0 * 25 + idx];
    if (tid < 48) bs[tid] = bias[c0 + tid];
    __syncthreads();

    if (tid < NN) {
        int y = tid / 14, x = tid % 14;
        float* orow = outb + ((size_t)b * NN + tid) * CC + h * HD + c0;
        for (int c = 0; c < 48; c++) {
            float s = bs[c];
#pragma unroll
            for (int dy = -2; dy <= 2; dy++) {
                int yy = y + dy;
                if ((unsigned)yy >= 14u) continue;
#pragma unroll
                for (int dx = -2; dx <= 2; dx++) {
                    int xx = x + dx;
                    if ((unsigned)xx >= 14u) continue;
                    s = fmaf(ws[c * 25 + (dy + 2) * 5 + (dx + 2)],
                             vs[(yy * 14 + xx) * 49 + c], s);
                }
            }
            orow[c] += s;
        }
    }
}

// ======================= launch =======================
extern "C" void kernel_launch(void* const* d_in, const int* in_sizes, int n_in,
                              void* d_out, int out_size)
{
    const float* x   = (const float*)d_in[0];
    const float* Wq  = (const float*)d_in[1];
    const float* bq  = (const float*)d_in[2];
    const float* Wk  = (const float*)d_in[3];
    const float* bk  = (const float*)d_in[4];
    const float* Wv  = (const float*)d_in[5];
    const float* bv  = (const float*)d_in[6];
    const float* pos = (const float*)d_in[7];
    const float* sp  = (const float*)d_in[8];
    const float* dw  = (const float*)d_in[9];
    const float* db  = (const float*)d_in[10];
    const float* Wp  = (const float*)d_in[11];
    const float* bp  = (const float*)d_in[12];
    float* out = (float*)d_out;

    float *Q, *K, *V, *Ab, *KV, *KS;
    cudaGetSymbolAddress((void**)&Q,  g_Q);
    cudaGetSymbolAddress((void**)&K,  g_K);
    cudaGetSymbolAddress((void**)&V,  g_V);
    cudaGetSymbolAddress((void**)&Ab, g_A);
    cudaGetSymbolAddress((void**)&KV, g_KV);
    cudaGetSymbolAddress((void**)&KS, g_KS);

    dim3 gg(CC / BN, MROWS / BM);   // (6, 196)

    sgemm_kernel<<<gg, 256>>>(x, Wq, bq, nullptr, Q, MROWS, CC, CC, 0);
    sgemm_kernel<<<gg, 256>>>(x, Wk, bk, pos,     K, MROWS, CC, CC, 1);
    sgemm_kernel<<<gg, 256>>>(x, Wv, bv, nullptr, V, MROWS, CC, CC, 0);

    focus_kernel<<<dim3(MROWS, 2), 256>>>(Q, K, sp);

    ksum_kernel<<<BHD, HD>>>(K, KS);
    kv_kernel<<<BHD, 256>>>(K, V, KV);
    attnout_kernel<<<BHD, 224>>>(Q, KV, KS, Ab);
    dwc_kernel<<<dim3(BHD, 2), 224>>>(V, dw, db, Ab);

    sgemm_kernel<<<gg, 256>>>(Ab, Wp, bp, nullptr, out, MROWS, CC, CC, 0);
}

// round 3
// speedup vs baseline: 1.8614x; 1.8614x over previous
#include <cuda_runtime.h>
#include <cuda_bf16.h>
#include <math.h>
#include <stdint.h>

// Problem constants
#define BB   128
#define NN   196
#define CC   768
#define HH   8
#define HD   96
#define MROWS (BB*NN)   // 25088
#define BHD   (BB*HH)   // 1024

// -------- device scratch (no runtime allocation allowed) --------
__device__ float g_Q[(size_t)MROWS*CC];
__device__ float g_K[(size_t)MROWS*CC];
__device__ float g_V[(size_t)MROWS*CC];
__device__ float g_A[(size_t)MROWS*CC];
__device__ float g_KV[(size_t)BHD*HD*HD];
__device__ float g_KS[(size_t)BHD*HD];
__device__ float g_invsc[CC];
__device__ __nv_bfloat16 g_xh[(size_t)MROWS*CC];
__device__ __nv_bfloat16 g_xl[(size_t)MROWS*CC];
__device__ __nv_bfloat16 g_ah[(size_t)MROWS*CC];
__device__ __nv_bfloat16 g_al[(size_t)MROWS*CC];
__device__ __nv_bfloat16 g_wh[(size_t)4*CC*CC];
__device__ __nv_bfloat16 g_wl[(size_t)4*CC*CC];

// ======================= PTX helpers =======================
__device__ __forceinline__ uint32_t s2u(const void* p) {
    uint32_t a;
    asm("{ .reg .u64 t; cvta.to.shared.u64 t, %1; cvt.u32.u64 %0, t; }" : "=r"(a) : "l"(p));
    return a;
}

#define CP16(d, s) asm volatile("cp.async.cg.shared.global [%0], [%1], 16;" :: "r"(d), "l"(s))
#define CP_COMMIT() asm volatile("cp.async.commit_group;" ::: "memory")
#define CP_WAIT(n)  asm volatile("cp.async.wait_group %0;" :: "n"(n) : "memory")

#define LDSM4(r0, r1, r2, r3, a) \
    asm volatile("ldmatrix.sync.aligned.m8n8.x4.shared.b16 {%0,%1,%2,%3}, [%4];" \
        : "=r"(r0), "=r"(r1), "=r"(r2), "=r"(r3) : "r"(a))

#define MMA(dp, a, b0, b1) \
    asm volatile("mma.sync.aligned.m16n8k16.row.col.f32.bf16.bf16.f32 " \
        "{%0,%1,%2,%3},{%4,%5,%6,%7},{%8,%9},{%0,%1,%2,%3};" \
        : "+f"((dp)[0]), "+f"((dp)[1]), "+f"((dp)[2]), "+f"((dp)[3]) \
        : "r"((a)[0]), "r"((a)[1]), "r"((a)[2]), "r"((a)[3]), "r"(b0), "r"(b1))

// smem chunk swizzle: element row r, 16B chunk c (0..3) -> byte offset
__device__ __forceinline__ uint32_t swoff(int r, int c) {
    return (uint32_t)(r * 64 + ((c ^ ((r >> 1) & 3)) << 4));
}

// ======================= split-bf16 mma.sync GEMM =======================
// C[M,768] = A[M,768] @ W ; W^T stored [N][K] K-contiguous, split hi/lo bf16.
// CTA tile 128x256, warp tile 64x64, BK=32, 4-stage cp.async pipeline.
#define GITERS 24
#define GSTG   4
#define STGB   49152
#define OAH    0
#define OAL    8192
#define OBH    16384
#define OBL    32768
#define SMEM_TOTAL_G (GSTG*STGB)  // 196608

__global__ __launch_bounds__(256, 1) void gemm_mma(
    const __nv_bfloat16* __restrict__ Ah, const __nv_bfloat16* __restrict__ Al,
    const __nv_bfloat16* __restrict__ Bh, const __nv_bfloat16* __restrict__ Bl,
    const float* __restrict__ bias, const float* __restrict__ pos,
    float* __restrict__ C, int addPos)
{
    extern __shared__ char smem[];
    const uint32_t sb = s2u(smem);
    const int tid  = threadIdx.x;
    const int lane = tid & 31;
    const int wid  = tid >> 5;
    const int wm   = (wid & 1) * 64;
    const int wn   = (wid >> 1) * 64;
    const int bm   = blockIdx.y * 128;
    const int bn   = blockIdx.x * 256;

#define LOAD_STAGE(s, kit) do {                                               \
    int k0 = (kit) * 32;                                                      \
    uint32_t st = sb + (uint32_t)(s) * STGB;                                  \
    _Pragma("unroll")                                                         \
    for (int i = 0; i < 2; i++) {                                             \
        int u = i * 256 + tid; int r = u >> 2, c = u & 3;                     \
        uint32_t so = swoff(r, c);                                            \
        size_t go = (size_t)(bm + r) * CC + k0 + c * 8;                       \
        CP16(st + OAH + so, Ah + go);                                         \
        CP16(st + OAL + so, Al + go);                                         \
    }                                                                         \
    _Pragma("unroll")                                                         \
    for (int i = 0; i < 4; i++) {                                             \
        int u = i * 256 + tid; int r = u >> 2, c = u & 3;                     \
        uint32_t so = swoff(r, c);                                            \
        size_t go = (size_t)(bn + r) * CC + k0 + c * 8;                       \
        CP16(st + OBH + so, Bh + go);                                         \
        CP16(st + OBL + so, Bl + go);                                         \
    }                                                                         \
    CP_COMMIT();                                                              \
} while (0)

    float acc[4][8][4];
#pragma unroll
    for (int a = 0; a < 4; a++)
#pragma unroll
        for (int b = 0; b < 8; b++)
#pragma unroll
            for (int c = 0; c < 4; c++) acc[a][b][c] = 0.f;

    // prologue: fill 3 stages
    LOAD_STAGE(0, 0);
    LOAD_STAGE(1, 1);
    LOAD_STAGE(2, 2);

    const int arow = lane & 15;       // A ldmatrix row within m16
    const int achk = lane >> 4;       // A k-chunk half
    const int brow = (lane & 7) + ((lane >> 4) & 1) * 8;  // B row within n16
    const int bchk = (lane >> 3) & 1; // B k-chunk half

    for (int it = 0; it < GITERS; ++it) {
        int rem = GITERS - 1 - it;
        if (rem >= 2) { CP_WAIT(2); }
        else if (rem == 1) { CP_WAIT(1); }
        else { CP_WAIT(0); }
        __syncthreads();

        int ld = it + GSTG - 1;
        if (ld < GITERS) LOAD_STAGE(ld & 3, ld);

        uint32_t st = sb + (uint32_t)(it & 3) * STGB;
#pragma unroll
        for (int kk = 0; kk < 2; kk++) {
            uint32_t ahf[4][4], alf[4][4];
#pragma unroll
            for (int mt = 0; mt < 4; mt++) {
                int row = wm + mt * 16 + arow;
                uint32_t off = swoff(row, kk * 2 + achk);
                LDSM4(ahf[mt][0], ahf[mt][1], ahf[mt][2], ahf[mt][3], st + OAH + off);
                LDSM4(alf[mt][0], alf[mt][1], alf[mt][2], alf[mt][3], st + OAL + off);
            }
#pragma unroll
            for (int bq = 0; bq < 4; bq++) {
                int row = wn + bq * 16 + brow;
                uint32_t off = swoff(row, kk * 2 + bchk);
                uint32_t bh0, bh1, bh2, bh3, bl0, bl1, bl2, bl3;
                LDSM4(bh0, bh1, bh2, bh3, st + OBH + off);
                LDSM4(bl0, bl1, bl2, bl3, st + OBL + off);
#pragma unroll
                for (int mt = 0; mt < 4; mt++) {
                    MMA(acc[mt][bq * 2],     ahf[mt], bh0, bh1);
                    MMA(acc[mt][bq * 2],     ahf[mt], bl0, bl1);
                    MMA(acc[mt][bq * 2],     alf[mt], bh0, bh1);
                    MMA(acc[mt][bq * 2 + 1], ahf[mt], bh2, bh3);
                    MMA(acc[mt][bq * 2 + 1], ahf[mt], bl2, bl3);
                    MMA(acc[mt][bq * 2 + 1], alf[mt], bh2, bh3);
                }
            }
        }
    }

    // epilogue: write acc + bias (+pos)
#pragma unroll
    for (int mt = 0; mt < 4; mt++) {
#pragma unroll
        for (int i = 0; i < 2; i++) {
            int grow = bm + wm + mt * 16 + (lane >> 2) + i * 8;
            int prow = grow % NN;
            float* crow = C + (size_t)grow * CC;
            const float* pr = pos + (size_t)prow * CC;
#pragma unroll
            for (int nq = 0; nq < 8; nq++) {
                int col = bn + wn + nq * 8 + (lane & 3) * 2;
                float2 o;
                o.x = acc[mt][nq][i * 2]     + bias[col];
                o.y = acc[mt][nq][i * 2 + 1] + bias[col + 1];
                if (addPos) {
                    o.x += pr[col];
                    o.y += pr[col + 1];
                }
                *(float2*)(crow + col) = o;
            }
        }
    }
#undef LOAD_STAGE
}

// ======================= weight transpose + bf16 split =======================
__global__ void wsplit_kernel(const float* __restrict__ W,
                              __nv_bfloat16* __restrict__ Wh, __nv_bfloat16* __restrict__ Wl)
{
    __shared__ float t[32][33];
    int n0 = blockIdx.x * 32, k0 = blockIdx.y * 32;
    int tx = threadIdx.x, ty = threadIdx.y;
#pragma unroll
    for (int i = 0; i < 4; i++)
        t[ty + 8 * i][tx] = W[(size_t)(k0 + ty + 8 * i) * CC + n0 + tx];
    __syncthreads();
#pragma unroll
    for (int i = 0; i < 4; i++) {
        float a = t[tx][ty + 8 * i];
        __nv_bfloat16 h = __float2bfloat16(a);
        __nv_bfloat16 l = __float2bfloat16(a - __bfloat162float(h));
        size_t o = (size_t)(n0 + ty + 8 * i) * CC + k0 + tx;
        Wh[o] = h; Wl[o] = l;
    }
}

// ======================= activation bf16 split =======================
__global__ __launch_bounds__(256) void split_kernel(
    const float4* __restrict__ A, __nv_bfloat162* __restrict__ Ah,
    __nv_bfloat162* __restrict__ Al, int n4)
{
    int i = blockIdx.x * 256 + threadIdx.x;
    if (i < n4) {
        float4 a = A[i];
        __nv_bfloat16 h0 = __float2bfloat16(a.x);
        __nv_bfloat16 h1 = __float2bfloat16(a.y);
        __nv_bfloat16 h2 = __float2bfloat16(a.z);
        __nv_bfloat16 h3 = __float2bfloat16(a.w);
        __nv_bfloat16 l0 = __float2bfloat16(a.x - __bfloat162float(h0));
        __nv_bfloat16 l1 = __float2bfloat16(a.y - __bfloat162float(h1));
        __nv_bfloat16 l2 = __float2bfloat16(a.z - __bfloat162float(h2));
        __nv_bfloat16 l3 = __float2bfloat16(a.w - __bfloat162float(h3));
        Ah[2 * i]     = __nv_bfloat162{h0, h1};
        Ah[2 * i + 1] = __nv_bfloat162{h2, h3};
        Al[2 * i]     = __nv_bfloat162{l0, l1};
        Al[2 * i + 1] = __nv_bfloat162{l2, l3};
    }
}

// ======================= inv softplus precompute =======================
__global__ void invsp_kernel(const float* __restrict__ sp)
{
    int c = blockIdx.x * 256 + threadIdx.x;
    if (c < CC) {
        float s = sp[c];
        float v = (s > 20.f) ? s : log1pf(expf(s));
        g_invsc[c] = 1.0f / v;
    }
}

// ======================= focusing kernel (float4, 192 thr) =======================
__global__ __launch_bounds__(192) void focus_kernel(float* __restrict__ q, float* __restrict__ k)
{
    float* t = blockIdx.y ? k : q;
    float4* p = (float4*)(t + (size_t)blockIdx.x * CC);
    const int tid = threadIdx.x;

    float4 x = p[tid];
    const float4 iv = ((const float4*)g_invsc)[tid];

    float v0 = (fmaxf(x.x, 0.f) + 1e-6f) * iv.x;
    float v1 = (fmaxf(x.y, 0.f) + 1e-6f) * iv.y;
    float v2 = (fmaxf(x.z, 0.f) + 1e-6f) * iv.z;
    float v3 = (fmaxf(x.w, 0.f) + 1e-6f) * iv.w;

    float a0 = v0 * v0, a1 = v1 * v1, a2 = v2 * v2, a3 = v3 * v3;
    float s2 = a0 + a1 + a2 + a3;
    float c0 = a0 * v0, c1 = a1 * v1, c2 = a2 * v2, c3 = a3 * v3;
    float s6 = c0 * c0 + c1 * c1 + c2 * c2 + c3 * c3;

    __shared__ float red2[6], red6[6];
    unsigned lane = tid & 31, w = tid >> 5;
#pragma unroll
    for (int o = 16; o > 0; o >>= 1) {
        s2 += __shfl_down_sync(0xffffffffu, s2, o);
        s6 += __shfl_down_sync(0xffffffffu, s6, o);
    }
    if (lane == 0) { red2[w] = s2; red6[w] = s6; }
    __syncthreads();
    float t2 = 0.f, t6 = 0.f;
#pragma unroll
    for (int i = 0; i < 6; i++) { t2 += red2[i]; t6 += red6[i]; }
    float f = sqrtf(t2 / t6);

    float4 o4;
    o4.x = c0 * f; o4.y = c1 * f; o4.z = c2 * f; o4.w = c3 * f;
    p[tid] = o4;
}

// ======================= ksum =======================
__global__ void ksum_kernel(const float* __restrict__ k, float* __restrict__ ksum)
{
    int bh = blockIdx.x;
    int b = bh >> 3, h = bh & 7;
    int c = threadIdx.x;
    const float* base = k + (size_t)b * NN * CC + h * HD + c;
    float s = 0.f;
#pragma unroll 4
    for (int j = 0; j < NN; j++) s += base[(size_t)j * CC];
    ksum[bh * HD + c] = s;
}

// ======================= kv = k^T v per (b,h) =======================
__global__ __launch_bounds__(256) void kv_kernel(
    const float* __restrict__ k, const float* __restrict__ v, float* __restrict__ kv)
{
    int bh = blockIdx.x;
    int b = bh >> 3, h = bh & 7;
    __shared__ float ks[28][HD];
    __shared__ float vs[28][HD];
    const int tid = threadIdx.x;
    const int ty = tid >> 4;
    const int tx = tid & 15;

    float acc[6][6];
#pragma unroll
    for (int i = 0; i < 6; i++)
#pragma unroll
        for (int j = 0; j < 6; j++) acc[i][j] = 0.f;

    const float* kb = k + (size_t)b * NN * CC + h * HD;
    const float* vb = v + (size_t)b * NN * CC + h * HD;

    for (int j0 = 0; j0 < NN; j0 += 28) {
        for (int idx = tid; idx < 28 * HD; idx += 256) {
            int j = idx / HD, c = idx % HD;
            ks[j][c] = kb[(size_t)(j0 + j) * CC + c];
            vs[j][c] = vb[(size_t)(j0 + j) * CC + c];
        }
        __syncthreads();
#pragma unroll 7
        for (int j = 0; j < 28; j++) {
            float kf[6], vf[6];
#pragma unroll
            for (int i = 0; i < 6; i++) kf[i] = ks[j][ty * 6 + i];
#pragma unroll
            for (int i = 0; i < 6; i++) vf[i] = vs[j][tx * 6 + i];
#pragma unroll
            for (int i = 0; i < 6; i++)
#pragma unroll
                for (int l = 0; l < 6; l++)
                    acc[i][l] = fmaf(kf[i], vf[l], acc[i][l]);
        }
        __syncthreads();
    }

#pragma unroll
    for (int i = 0; i < 6; i++)
#pragma unroll
        for (int l = 0; l < 6; l++)
            kv[(size_t)bh * HD * HD + (ty * 6 + i) * HD + tx * 6 + l] = acc[i][l];
}

// ======================= attention output (z fused) =======================
__global__ __launch_bounds__(224) void attnout_kernel(
    const float* __restrict__ q, const float* __restrict__ kv,
    const float* __restrict__ ksum, float* __restrict__ outb)
{
    int bh = blockIdx.x;
    int b = bh >> 3, h = bh & 7;
    __shared__ __align__(16) float kvs[HD * HD];
    __shared__ float ksm[HD];
    const int tid = threadIdx.x;

    for (int idx = tid; idx < HD * HD; idx += 224)
        kvs[idx] = kv[(size_t)bh * HD * HD + idx];
    if (tid < HD) ksm[tid] = ksum[bh * HD + tid];
    __syncthreads();

    if (tid < NN) {
        const float* qr = q + ((size_t)b * NN + tid) * CC + h * HD;
        float zi = 0.f;
#pragma unroll 8
        for (int c = 0; c < HD; c++) zi += qr[c] * ksm[c];
        zi = 1.f / (zi + 1e-6f);

        float4 acc[24];
#pragma unroll
        for (int d = 0; d < 24; d++) acc[d] = make_float4(0.f, 0.f, 0.f, 0.f);

        for (int c = 0; c < HD; c++) {
            float qv = qr[c];
            const float4* kr = (const float4*)(kvs + c * HD);
#pragma unroll
            for (int d = 0; d < 24; d++) {
                float4 k4 = kr[d];
                acc[d].x = fmaf(qv, k4.x, acc[d].x);
                acc[d].y = fmaf(qv, k4.y, acc[d].y);
                acc[d].z = fmaf(qv, k4.z, acc[d].z);
                acc[d].w = fmaf(qv, k4.w, acc[d].w);
            }
        }

        float* orow = outb + ((size_t)b * NN + tid) * CC + h * HD;
#pragma unroll
        for (int d = 0; d < 24; d++) {
            float4 r = acc[d];
            r.x *= zi; r.y *= zi; r.z *= zi; r.w *= zi;
            *(float4*)(orow + d * 4) = r;
        }
    }
}

// ======================= depthwise 5x5 conv on v (14x14) =======================
__global__ __launch_bounds__(224) void dwc_kernel(
    const float* __restrict__ v, const float* __restrict__ w,
    const float* __restrict__ bias, float* __restrict__ outb)
{
    int bh = blockIdx.x;
    int b = bh >> 3, h = bh & 7;
    int c0 = blockIdx.y * 48;

    __shared__ float vs[NN * 49];
    __shared__ float ws[48 * 25];
    __shared__ float bs[48];
    const int tid = threadIdx.x;

    for (int idx = tid; idx < NN * 48; idx += 224) {
        int p = idx / 48, c = idx % 48;
        vs[p * 49 + c] = v[((size_t)b * NN + p) * CC + h * HD + c0 + c];
    }
    for (int idx = tid; idx < 48 * 25; idx += 224) ws[idx] = w[c0 * 25 + idx];
    if (tid < 48) bs[tid] = bias[c0 + tid];
    __syncthreads();

    if (tid < NN) {
        int y = tid / 14, x = tid % 14;
        float* orow = outb + ((size_t)b * NN + tid) * CC + h * HD + c0;
        for (int c = 0; c < 48; c++) {
            float s = bs[c];
#pragma unroll
            for (int dy = -2; dy <= 2; dy++) {
                int yy = y + dy;
                if ((unsigned)yy >= 14u) continue;
#pragma unroll
                for (int dx = -2; dx <= 2; dx++) {
                    int xx = x + dx;
                    if ((unsigned)xx >= 14u) continue;
                    s = fmaf(ws[c * 25 + (dy + 2) * 5 + (dx + 2)],
                             vs[(yy * 14 + xx) * 49 + c], s);
                }
            }
            orow[c] += s;
        }
    }
}

// ======================= launch =======================
extern "C" void kernel_launch(void* const* d_in, const int* in_sizes, int n_in,
                              void* d_out, int out_size)
{
    const float* x   = (const float*)d_in[0];
    const float* Wq  = (const float*)d_in[1];
    const float* bq  = (const float*)d_in[2];
    const float* Wk  = (const float*)d_in[3];
    const float* bk  = (const float*)d_in[4];
    const float* Wv  = (const float*)d_in[5];
    const float* bv  = (const float*)d_in[6];
    const float* pos = (const float*)d_in[7];
    const float* sp  = (const float*)d_in[8];
    const float* dw  = (const float*)d_in[9];
    const float* db  = (const float*)d_in[10];
    const float* Wp  = (const float*)d_in[11];
    const float* bp  = (const float*)d_in[12];
    float* out = (float*)d_out;

    float *Q, *K, *V, *Ab, *KV, *KS;
    __nv_bfloat16 *xh, *xl, *ah, *al, *wh, *wl;
    cudaGetSymbolAddress((void**)&Q,  g_Q);
    cudaGetSymbolAddress((void**)&K,  g_K);
    cudaGetSymbolAddress((void**)&V,  g_V);
    cudaGetSymbolAddress((void**)&Ab, g_A);
    cudaGetSymbolAddress((void**)&KV, g_KV);
    cudaGetSymbolAddress((void**)&KS, g_KS);
    cudaGetSymbolAddress((void**)&xh, g_xh);
    cudaGetSymbolAddress((void**)&xl, g_xl);
    cudaGetSymbolAddress((void**)&ah, g_ah);
    cudaGetSymbolAddress((void**)&al, g_al);
    cudaGetSymbolAddress((void**)&wh, g_wh);
    cudaGetSymbolAddress((void**)&wl, g_wl);

    cudaFuncSetAttribute(gemm_mma, cudaFuncAttributeMaxDynamicSharedMemorySize, SMEM_TOTAL_G);

    const size_t WSZ = (size_t)CC * CC;
    dim3 wgrid(24, 24), wblk(32, 8);
    wsplit_kernel<<<wgrid, wblk>>>(Wq, wh + 0 * WSZ, wl + 0 * WSZ);
    wsplit_kernel<<<wgrid, wblk>>>(Wk, wh + 1 * WSZ, wl + 1 * WSZ);
    wsplit_kernel<<<wgrid, wblk>>>(Wv, wh + 2 * WSZ, wl + 2 * WSZ);
    wsplit_kernel<<<wgrid, wblk>>>(Wp, wh + 3 * WSZ, wl + 3 * WSZ);

    const int n4 = MROWS * CC / 4;
    split_kernel<<<(n4 + 255) / 256, 256>>>((const float4*)x,
        (__nv_bfloat162*)xh, (__nv_bfloat162*)xl, n4);
    invsp_kernel<<<3, 256>>>(sp);

    dim3 gg(CC / 256, MROWS / 128);   // (3, 196)
    gemm_mma<<<gg, 256, SMEM_TOTAL_G>>>(xh, xl, wh + 0 * WSZ, wl + 0 * WSZ, bq, pos, Q, 0);
    gemm_mma<<<gg, 256, SMEM_TOTAL_G>>>(xh, xl, wh + 1 * WSZ, wl + 1 * WSZ, bk, pos, K, 1);
    gemm_mma<<<gg, 256, SMEM_TOTAL_G>>>(xh, xl, wh + 2 * WSZ, wl + 2 * WSZ, bv, pos, V, 0);

    focus_kernel<<<dim3(MROWS, 2), 192>>>(Q, K);

    ksum_kernel<<<BHD, HD>>>(K, KS);
    kv_kernel<<<BHD, 256>>>(K, V, KV);
    attnout_kernel<<<BHD, 224>>>(Q, KV, KS, Ab);
    dwc_kernel<<<dim3(BHD, 2), 224>>>(V, dw, db, Ab);

    split_kernel<<<(n4 + 255) / 256, 256>>>((const float4*)Ab,
        (__nv_bfloat162*)ah, (__nv_bfloat162*)al, n4);
    gemm_mma<<<gg, 256, SMEM_TOTAL_G>>>(ah, al, wh + 3 * WSZ, wl + 3 * WSZ, bp, pos, out, 0);
}